// round 8
// baseline (speedup 1.0000x reference)
#include <cuda_runtime.h>

#define RAD_N 5
#define AZI_N 30
#define ELE_N 15
#define NBINS (RAD_N * AZI_N * ELE_N)   // 2250
#define BPB   32                        // blocks per batch
#define TPB   512

__global__ void zero_kernel(float* __restrict__ out, int n) {
    int i = blockIdx.x * blockDim.x + threadIdx.x;
    if (i < n) out[i] = 0.0f;
}

// Analytic two-nearest-bin for uniform bins with centers (j+0.5)*step.
// u = value/step. Interior: w1 = 1-|f-0.5|, w2 = |f-0.5|, j2 = j1 +/- 1.
// Out-of-range j2 fixed up by caller per the reference's boundary rules.
__device__ __forceinline__ void axis2(float u, int N,
                                      int& j1, int& j2, float& w1, float& w2) {
    int j = (int)u;                 // u >= 0 always
    if (j > N - 1) j = N - 1;       // u == N edge (and float rounding)
    float f = u - (float)j;
    j1 = j;
    if (f < 0.5f) { j2 = j - 1; w1 = 0.5f + f; w2 = 0.5f - f; }
    else          { j2 = j + 1; w1 = 1.5f - f; w2 = f - 0.5f; }
}

__device__ __forceinline__ void accum_point(float x, float y, float z,
                                            float* __restrict__ hist) {
    const float TWO_PI = 6.28318530717958647692f;
    const float PIF    = 3.14159265358979323846f;
    const float inv_tr = (float)RAD_N / 2.0f;
    const float inv_ta = (float)AZI_N / TWO_PI;
    const float inv_te = (float)ELE_N / PIF;

    float r = sqrtf(fmaf(x, x, fmaf(y, y, z * z)));
    if (r > 2.0f) return;   // both radial weights forced to 0 by reference

    float azi = atan2f(y, x);
    if (azi < 0.0f) azi += TWO_PI;
    float c = z / fmaxf(r, 1e-12f);
    float ele = acosf(fminf(fmaxf(c, -1.0f), 1.0f));

    // ---- radial ----
    int ri1, ri2; float wr0, wr1;
    axis2(r * inv_tr, RAD_N, ri1, ri2, wr0, wr1);
    if (ri2 < 0)               { wr0 = 1.0f; wr1 = 0.0f; ri2 = 1; }          // r < sr
    else if (ri2 > RAD_N - 1)  { wr1 = 0.0f; ri2 = RAD_N - 2; }              // r > 2 - sr

    // ---- azimuth (circular) ----
    int ai1, ai2; float wa0, wa1;
    axis2(azi * inv_ta, AZI_N, ai1, ai2, wa0, wa1);
    if (ai2 < 0) ai2 = AZI_N - 1;
    else if (ai2 > AZI_N - 1) ai2 = 0;

    // ---- elevation ----
    int ei1, ei2; float we0, we1;
    axis2(ele * inv_te, ELE_N, ei1, ei2, we0, we1);
    if (ei2 < 0)               { we0 = 1.0f; we1 = 0.0f; ei2 = 1; }          // ele < se
    else if (ei2 > ELE_N - 1)  { we0 = 1.0f; we1 = 0.0f; ei2 = ELE_N - 2; }  // ele > pi - se

    // ---- 8 trilinear scatter-adds into the shared histogram ----
    const int b00 = (ri1 * AZI_N + ai1) * ELE_N;
    const int b01 = (ri1 * AZI_N + ai2) * ELE_N;
    const int b10 = (ri2 * AZI_N + ai1) * ELE_N;
    const int b11 = (ri2 * AZI_N + ai2) * ELE_N;
    const float w00 = wr0 * wa0;
    const float w01 = wr0 * wa1;
    const float w10 = wr1 * wa0;
    const float w11 = wr1 * wa1;

    atomicAdd(&hist[b00 + ei1], w00 * we0);
    atomicAdd(&hist[b00 + ei2], w00 * we1);
    atomicAdd(&hist[b01 + ei1], w01 * we0);
    atomicAdd(&hist[b01 + ei2], w01 * we1);
    atomicAdd(&hist[b10 + ei1], w10 * we0);
    atomicAdd(&hist[b10 + ei2], w10 * we1);
    atomicAdd(&hist[b11 + ei1], w11 * we0);
    atomicAdd(&hist[b11 + ei2], w11 * we1);
}

__global__ __launch_bounds__(TPB, 4)
void vox_kernel(const float* __restrict__ pts, float* __restrict__ out, int npts_per_batch) {
    __shared__ float hist[NBINS];
    for (int i = threadIdx.x; i < NBINS; i += TPB) hist[i] = 0.0f;
    __syncthreads();

    const int batch = blockIdx.y;
    const int chunk = blockIdx.x;

    // Each thread owns groups of 4 consecutive points -> 3 aligned float4 loads.
    // Batch base byte offset = batch * npts * 12, divisible by 16 for npts%4==0.
    const float4* __restrict__ bp4 =
        (const float4*)(pts + (long)batch * npts_per_batch * 3);
    const int ngroups = npts_per_batch >> 2;

    for (int g = chunk * TPB + threadIdx.x; g < ngroups; g += BPB * TPB) {
        const float4 A = bp4[g * 3 + 0];
        const float4 B = bp4[g * 3 + 1];
        const float4 C = bp4[g * 3 + 2];

        accum_point(A.x, A.y, A.z, hist);
        accum_point(A.w, B.x, B.y, hist);
        accum_point(B.z, B.w, C.x, hist);
        accum_point(C.y, C.z, C.w, hist);
    }

    __syncthreads();

    // ---- flush shared histogram into the global per-batch histogram ----
    float* __restrict__ ob = out + batch * NBINS;
    for (int i = threadIdx.x; i < NBINS; i += TPB) {
        float v = hist[i];
        if (v != 0.0f) atomicAdd(&ob[i], v);
    }
}

extern "C" void kernel_launch(void* const* d_in, const int* in_sizes, int n_in,
                              void* d_out, int out_size) {
    const float* pts = (const float*)d_in[0];
    float* out = (float*)d_out;

    const int batches = out_size / NBINS;                 // 16
    const int npts    = in_sizes[0] / (3 * batches);      // 65536

    zero_kernel<<<(out_size + 255) / 256, 256>>>(out, out_size);

    dim3 grid(BPB, batches);                              // 512 CTAs, 16 warps each
    vox_kernel<<<grid, TPB>>>(pts, out, npts);
}

// round 11
// speedup vs baseline: 1.0137x; 1.0137x over previous
#include <cuda_runtime.h>

#define RAD_N 5
#define AZI_N 30
#define ELE_N 15
#define NBINS (RAD_N * AZI_N * ELE_N)   // 2250
#define BPB   32                        // blocks per batch
#define TPB   512

__global__ void zero_kernel(float* __restrict__ out, int n) {
    int i = blockIdx.x * blockDim.x + threadIdx.x;
    if (i < n) out[i] = 0.0f;
}

// Octant-folded polynomial atan2. Max abs error ~1e-6 rad.
// Returns value in (-pi, pi]; (0,0) -> 0.
__device__ __forceinline__ float fast_atan2(float y, float x) {
    const float PIF  = 3.14159265358979f;
    const float PI_2 = 1.57079632679490f;
    float ax = fabsf(x), ay = fabsf(y);
    float mx = fmaxf(ax, ay), mn = fminf(ax, ay);
    float t = (mx == 0.0f) ? 0.0f : __fdividef(mn, mx);   // [0,1]; guard (0,0)
    float s = t * t;
    float p = -0.0117212f;
    p = fmaf(p, s,  0.05265332f);
    p = fmaf(p, s, -0.11643287f);
    p = fmaf(p, s,  0.19354346f);
    p = fmaf(p, s, -0.33262347f);
    p = fmaf(p, s,  0.99997726f);
    p = p * t;
    if (ay > ax)  p = PI_2 - p;
    if (x < 0.0f) p = PIF - p;
    if (y < 0.0f) p = -p;
    return p;
}

// Analytic two-nearest-bin for uniform bins with centers (j+0.5)*step.
__device__ __forceinline__ void axis2(float u, int N,
                                      int& j1, int& j2, float& w1, float& w2) {
    int j = (int)u;                 // u >= 0 always
    if (j > N - 1) j = N - 1;       // u == N edge (float rounding)
    float f = u - (float)j;
    j1 = j;
    if (f < 0.5f) { j2 = j - 1; w1 = 0.5f + f; w2 = 0.5f - f; }
    else          { j2 = j + 1; w1 = 1.5f - f; w2 = f - 0.5f; }
}

__device__ __forceinline__ void accum_point(float x, float y, float z,
                                            float* __restrict__ hist) {
    const float TWO_PI = 6.28318530717958647692f;
    const float PIF    = 3.14159265358979323846f;
    const float inv_tr = (float)RAD_N / 2.0f;
    const float inv_ta = (float)AZI_N / TWO_PI;
    const float inv_te = (float)ELE_N / PIF;

    float rxy2 = fmaf(y, y, x * x);
    float r = sqrtf(rxy2 + z * z);
    if (r > 2.0f) return;   // both radial weights forced to 0 by reference

    float azi = fast_atan2(y, x);
    if (azi < 0.0f) azi += TWO_PI;
    // ele = acos(z/r) == atan2(sqrt(x^2+y^2), z), exactly, range [0, pi]
    float ele = fast_atan2(sqrtf(rxy2), z);

    // ---- radial ----
    int ri1, ri2; float wr0, wr1;
    axis2(r * inv_tr, RAD_N, ri1, ri2, wr0, wr1);
    if (ri2 < 0)               { wr0 = 1.0f; wr1 = 0.0f; ri2 = 1; }          // r < sr
    else if (ri2 > RAD_N - 1)  { wr1 = 0.0f; ri2 = RAD_N - 2; }              // r > 2 - sr

    // ---- azimuth (circular) ----
    int ai1, ai2; float wa0, wa1;
    axis2(azi * inv_ta, AZI_N, ai1, ai2, wa0, wa1);
    if (ai2 < 0) ai2 = AZI_N - 1;
    else if (ai2 > AZI_N - 1) ai2 = 0;

    // ---- elevation ----
    int ei1, ei2; float we0, we1;
    axis2(ele * inv_te, ELE_N, ei1, ei2, we0, we1);
    if (ei2 < 0)               { we0 = 1.0f; we1 = 0.0f; ei2 = 1; }          // ele < se
    else if (ei2 > ELE_N - 1)  { we0 = 1.0f; we1 = 0.0f; ei2 = ELE_N - 2; }  // ele > pi - se

    // ---- 8 trilinear scatter-adds into the shared histogram ----
    const int b00 = (ri1 * AZI_N + ai1) * ELE_N;
    const int b01 = (ri1 * AZI_N + ai2) * ELE_N;
    const int b10 = (ri2 * AZI_N + ai1) * ELE_N;
    const int b11 = (ri2 * AZI_N + ai2) * ELE_N;
    const float w00 = wr0 * wa0;
    const float w01 = wr0 * wa1;
    const float w10 = wr1 * wa0;
    const float w11 = wr1 * wa1;

    atomicAdd(&hist[b00 + ei1], w00 * we0);
    atomicAdd(&hist[b00 + ei2], w00 * we1);
    atomicAdd(&hist[b01 + ei1], w01 * we0);
    atomicAdd(&hist[b01 + ei2], w01 * we1);
    atomicAdd(&hist[b10 + ei1], w10 * we0);
    atomicAdd(&hist[b10 + ei2], w10 * we1);
    atomicAdd(&hist[b11 + ei1], w11 * we0);
    atomicAdd(&hist[b11 + ei2], w11 * we1);
}

__global__ __launch_bounds__(TPB, 4)
void vox_kernel(const float* __restrict__ pts, float* __restrict__ out, int npts_per_batch) {
    __shared__ float hist[NBINS];
    for (int i = threadIdx.x; i < NBINS; i += TPB) hist[i] = 0.0f;
    __syncthreads();

    const int batch = blockIdx.y;
    const int chunk = blockIdx.x;

    // Each thread owns groups of 4 consecutive points -> 3 aligned float4 loads.
    const float4* __restrict__ bp4 =
        (const float4*)(pts + (long)batch * npts_per_batch * 3);
    const int ngroups = npts_per_batch >> 2;

    for (int g = chunk * TPB + threadIdx.x; g < ngroups; g += BPB * TPB) {
        const float4 A = bp4[g * 3 + 0];
        const float4 B = bp4[g * 3 + 1];
        const float4 C = bp4[g * 3 + 2];

        accum_point(A.x, A.y, A.z, hist);
        accum_point(A.w, B.x, B.y, hist);
        accum_point(B.z, B.w, C.x, hist);
        accum_point(C.y, C.z, C.w, hist);
    }

    __syncthreads();

    // ---- flush shared histogram into the global per-batch histogram ----
    float* __restrict__ ob = out + batch * NBINS;
    for (int i = threadIdx.x; i < NBINS; i += TPB) {
        float v = hist[i];
        if (v != 0.0f) atomicAdd(&ob[i], v);
    }
}

extern "C" void kernel_launch(void* const* d_in, const int* in_sizes, int n_in,
                              void* d_out, int out_size) {
    const float* pts = (const float*)d_in[0];
    float* out = (float*)d_out;

    const int batches = out_size / NBINS;                 // 16
    const int npts    = in_sizes[0] / (3 * batches);      // 65536

    zero_kernel<<<(out_size + 255) / 256, 256>>>(out, out_size);

    dim3 grid(BPB, batches);                              // 512 CTAs, 16 warps each
    vox_kernel<<<grid, TPB>>>(pts, out, npts);
}

// round 16
// speedup vs baseline: 1.1067x; 1.0917x over previous
#include <cuda_runtime.h>

#define RAD_N 5
#define AZI_N 30
#define ELE_N 15
#define NBINS (RAD_N * AZI_N * ELE_N)   // 2250
#define NROWS (RAD_N * AZI_N)           // 150 (r,a) rows
#define PAIRS 7                         // ele pairs per parity per row
#define NP    (NROWS * PAIRS)           // 1050
#define BPB   32                        // blocks per batch
#define TPB   512

#define SCALE     4194304.0f            // 2^22
#define INV_SCALE (1.0f / 4194304.0f)

__global__ void zero_kernel(float* __restrict__ out, int n) {
    int i = blockIdx.x * blockDim.x + threadIdx.x;
    if (i < n) out[i] = 0.0f;
}

// Octant-folded polynomial atan2. Max abs error ~1e-6 rad. (0,0) -> 0.
__device__ __forceinline__ float fast_atan2(float y, float x) {
    const float PIF  = 3.14159265358979f;
    const float PI_2 = 1.57079632679490f;
    float ax = fabsf(x), ay = fabsf(y);
    float mx = fmaxf(ax, ay), mn = fminf(ax, ay);
    float t = (mx == 0.0f) ? 0.0f : __fdividef(mn, mx);
    float s = t * t;
    float p = -0.0117212f;
    p = fmaf(p, s,  0.05265332f);
    p = fmaf(p, s, -0.11643287f);
    p = fmaf(p, s,  0.19354346f);
    p = fmaf(p, s, -0.33262347f);
    p = fmaf(p, s,  0.99997726f);
    p = p * t;
    if (ay > ax)  p = PI_2 - p;
    if (x < 0.0f) p = PIF - p;
    if (y < 0.0f) p = -p;
    return p;
}

// Analytic two-nearest-bin for uniform bins with centers (j+0.5)*step.
__device__ __forceinline__ void axis2(float u, int N,
                                      int& j1, int& j2, float& w1, float& w2) {
    int j = (int)u;
    if (j > N - 1) j = N - 1;
    float f = u - (float)j;
    j1 = j;
    if (f < 0.5f) { j2 = j - 1; w1 = 0.5f + f; w2 = 0.5f - f; }
    else          { j2 = j + 1; w1 = 1.5f - f; w2 = f - 0.5f; }
}

// hist layout: [parity][row][pair] as u64; parity A=even e0, B=odd e0.
// A pair k of a row covers cells (2k lo, 2k+1 hi); B pair k covers (2k+1 lo, 2k+2 hi).
__device__ __forceinline__ void accum_point(float x, float y, float z,
                                            unsigned long long* __restrict__ hist) {
    const float TWO_PI = 6.28318530717958647692f;
    const float PIF    = 3.14159265358979323846f;
    const float inv_tr = (float)RAD_N / 2.0f;
    const float inv_ta = (float)AZI_N / TWO_PI;
    const float inv_te = (float)ELE_N / PIF;

    float rxy2 = fmaf(y, y, x * x);
    float r = sqrtf(rxy2 + z * z);
    if (r > 2.0f) return;

    float azi = fast_atan2(y, x);
    if (azi < 0.0f) azi += TWO_PI;
    float ele = fast_atan2(sqrtf(rxy2), z);   // == acos(z/r), range [0, pi]

    // ---- radial ----
    int ri1, ri2; float wr0, wr1;
    axis2(r * inv_tr, RAD_N, ri1, ri2, wr0, wr1);
    if (ri2 < 0)               { wr0 = 1.0f; wr1 = 0.0f; ri2 = 1; }
    else if (ri2 > RAD_N - 1)  { wr1 = 0.0f; ri2 = RAD_N - 2; }

    // ---- azimuth (circular) ----
    int ai1, ai2; float wa0, wa1;
    axis2(azi * inv_ta, AZI_N, ai1, ai2, wa0, wa1);
    if (ai2 < 0) ai2 = AZI_N - 1;
    else if (ai2 > AZI_N - 1) ai2 = 0;

    // ---- elevation ----
    int ei1, ei2; float we0, we1;
    axis2(ele * inv_te, ELE_N, ei1, ei2, we0, we1);
    if (ei2 < 0)               { we0 = 1.0f; we1 = 0.0f; ei2 = 1; }
    else if (ei2 > ELE_N - 1)  { we0 = 1.0f; we1 = 0.0f; ei2 = ELE_N - 2; }

    // Elevation pair is always adjacent: {e0, e0+1}.
    int e0 = min(ei1, ei2);
    float wl = (ei1 <= ei2) ? we0 : we1;     // weight for cell e0
    float wh = (ei1 <= ei2) ? we1 : we0;     // weight for cell e0+1

    // Base offset: parity selects A/B half, k = e0>>1 works for both parities.
    const int pbase = (e0 & 1) * NP + (e0 >> 1);
    const int p00 = pbase + (ri1 * AZI_N + ai1) * PAIRS;
    const int p01 = pbase + (ri1 * AZI_N + ai2) * PAIRS;
    const int p10 = pbase + (ri2 * AZI_N + ai1) * PAIRS;
    const int p11 = pbase + (ri2 * AZI_N + ai2) * PAIRS;

    const float w00 = wr0 * wa0;
    const float w01 = wr0 * wa1;

    // pack(lo, hi): lo cell in bits [0,32), hi cell in bits [32,64).
    unsigned long long v00 = (unsigned long long)__float2uint_rn(w00 * wl * SCALE)
                           | ((unsigned long long)__float2uint_rn(w00 * wh * SCALE) << 32);
    unsigned long long v01 = (unsigned long long)__float2uint_rn(w01 * wl * SCALE)
                           | ((unsigned long long)__float2uint_rn(w01 * wh * SCALE) << 32);
    atomicAdd(&hist[p00], v00);
    atomicAdd(&hist[p01], v01);

    if (wr1 != 0.0f) {   // ~10% of points sit in the outer half-bin band where wr1==0
        const float w10 = wr1 * wa0;
        const float w11 = wr1 * wa1;
        unsigned long long v10 = (unsigned long long)__float2uint_rn(w10 * wl * SCALE)
                               | ((unsigned long long)__float2uint_rn(w10 * wh * SCALE) << 32);
        unsigned long long v11 = (unsigned long long)__float2uint_rn(w11 * wl * SCALE)
                               | ((unsigned long long)__float2uint_rn(w11 * wh * SCALE) << 32);
        atomicAdd(&hist[p10], v10);
        atomicAdd(&hist[p11], v11);
    }
}

__global__ __launch_bounds__(TPB, 4)
void vox_kernel(const float* __restrict__ pts, float* __restrict__ out, int npts_per_batch) {
    __shared__ unsigned long long hist[2 * NP];   // 16.8 KB
    for (int i = threadIdx.x; i < 2 * NP; i += TPB) hist[i] = 0ull;
    __syncthreads();

    const int batch = blockIdx.y;
    const int chunk = blockIdx.x;

    const float4* __restrict__ bp4 =
        (const float4*)(pts + (long)batch * npts_per_batch * 3);
    const int ngroups = npts_per_batch >> 2;

    for (int g = chunk * TPB + threadIdx.x; g < ngroups; g += BPB * TPB) {
        const float4 A = bp4[g * 3 + 0];
        const float4 B = bp4[g * 3 + 1];
        const float4 C = bp4[g * 3 + 2];

        accum_point(A.x, A.y, A.z, hist);
        accum_point(A.w, B.x, B.y, hist);
        accum_point(B.z, B.w, C.x, hist);
        accum_point(C.y, C.z, C.w, hist);
    }

    __syncthreads();

    // ---- decode staggered pairs and flush to the global per-batch histogram ----
    float* __restrict__ ob = out + batch * NBINS;
    for (int i = threadIdx.x; i < NBINS; i += TPB) {
        const int row = i / ELE_N;
        const int e   = i - row * ELE_N;
        unsigned int c = 0;
        if (e < ELE_N - 1) {   // A half covers cells 0..13
            unsigned long long va = hist[row * PAIRS + (e >> 1)];
            c += (e & 1) ? (unsigned int)(va >> 32) : (unsigned int)va;
        }
        if (e > 0) {           // B half covers cells 1..14
            unsigned long long vb = (e & 1)
                ? hist[NP + row * PAIRS + (e >> 1)]
                : hist[NP + row * PAIRS + (e >> 1) - 1];
            c += (e & 1) ? (unsigned int)vb : (unsigned int)(vb >> 32);
        }
        if (c) atomicAdd(&ob[i], (float)c * INV_SCALE);
    }
}

extern "C" void kernel_launch(void* const* d_in, const int* in_sizes, int n_in,
                              void* d_out, int out_size) {
    const float* pts = (const float*)d_in[0];
    float* out = (float*)d_out;

    const int batches = out_size / NBINS;                 // 16
    const int npts    = in_sizes[0] / (3 * batches);      // 65536

    zero_kernel<<<(out_size + 255) / 256, 256>>>(out, out_size);

    dim3 grid(BPB, batches);                              // 512 CTAs, 16 warps each
    vox_kernel<<<grid, TPB>>>(pts, out, npts);
}